// round 13
// baseline (speedup 1.0000x reference)
#include <cuda_runtime.h>
#include <cuda_fp16.h>
#include <cstdint>

// Problem dims
#define M_DIM 8192
#define N_DIM 4096
#define K_DIM 4096
#define CAP_  1024

// GEMM tiling (128x128, 256 thr, 2 CTAs/SM)
#define BM 128
#define BN 128
#define BK 64
#define KT (K_DIM / BK)            // 64
#define STAGES 3
#define PAD 72                     // smem row pitch in elements (144B rows)
#define TILE_BYTES (128 * PAD * 2) // 18432
#define STAGE_BYTES (2 * TILE_BYTES)          // A + B = 36864
#define SMEM_TOTAL (STAGES * STAGE_BYTES)     // 110592 -> 2 CTAs/SM

#define OFF_A 0
#define OFF_B TILE_BYTES

// ---------------------------------------------------------------------------
// Scratch (static device memory)
// ---------------------------------------------------------------------------
__device__ __half g_Xh[(size_t)M_DIM * K_DIM];   // x rounded to fp16
__device__ __half g_Wh[(size_t)N_DIM * K_DIM];   // w*scale rounded to fp16
__device__ float g_logits[CAP_];
__device__ float g_memout[N_DIM];

// ---------------------------------------------------------------------------
__device__ __forceinline__ unsigned smem_u32(const void* p) {
    return (unsigned)__cvta_generic_to_shared(p);
}
__device__ __forceinline__ void cp16(unsigned sa, const void* ga) {
    asm volatile("cp.async.cg.shared.global [%0], [%1], 16;" :: "r"(sa), "l"(ga));
}

// ---------------------------------------------------------------------------
// Prep: x -> fp16; w*scale -> fp16
// ---------------------------------------------------------------------------
__global__ void split_x_kernel(const float* __restrict__ x, int n2) {
    int i = blockIdx.x * blockDim.x + threadIdx.x;
    int stride = gridDim.x * blockDim.x;
    const float2* x2 = reinterpret_cast<const float2*>(x);
    __half2* h2 = reinterpret_cast<__half2*>(g_Xh);
    for (; i < n2; i += stride) {
        float2 v = x2[i];
        h2[i] = __floats2half2_rn(v.x, v.y);
    }
}

__global__ void split_w_kernel(const float* __restrict__ w,
                               const float* __restrict__ scale, int n2) {
    int i = blockIdx.x * blockDim.x + threadIdx.x;
    int stride = gridDim.x * blockDim.x;
    const float2* w2 = reinterpret_cast<const float2*>(w);
    __half2* hi2 = reinterpret_cast<__half2*>(g_Wh);
    for (; i < n2; i += stride) {
        float2 v = w2[i];
        int row = i >> 11;             // (2*i)/4096
        float s = scale[row];
        hi2[i] = __floats2half2_rn(v.x * s, v.y * s);
    }
}

// ---------------------------------------------------------------------------
// Associative memory
// ---------------------------------------------------------------------------
__global__ void logits_kernel(const float* __restrict__ keys,
                              const float* __restrict__ x) {
    int c = blockIdx.x;
    const float* kr = keys + (size_t)c * K_DIM;
    float s = 0.f;
    for (int i = threadIdx.x; i < K_DIM; i += 128) s += kr[i] * x[i];
    for (int o = 16; o; o >>= 1) s += __shfl_xor_sync(0xffffffffu, s, o);
    __shared__ float red[4];
    if ((threadIdx.x & 31) == 0) red[threadIdx.x >> 5] = s;
    __syncthreads();
    if (threadIdx.x == 0) g_logits[c] = red[0] + red[1] + red[2] + red[3];
}

// Fused softmax + attn@V: 512 CTAs x 256 threads; CTA owns 8 output cols;
// threads split CAP into 32 chunks of 32; deterministic smem reduce.
__global__ void memout_kernel(const float* __restrict__ V) {
    __shared__ float se[CAP_];
    __shared__ float red[8];
    __shared__ float part[32][9];
    const int t = threadIdx.x;       // 256 threads

    float lmax = -1e30f;
    float lv[4];
    #pragma unroll
    for (int j = 0; j < 4; ++j) {
        lv[j] = g_logits[t + j * 256];
        lmax = fmaxf(lmax, lv[j]);
    }
    for (int o = 16; o; o >>= 1) lmax = fmaxf(lmax, __shfl_xor_sync(0xffffffffu, lmax, o));
    if ((t & 31) == 0) red[t >> 5] = lmax;
    __syncthreads();
    float m = fmaxf(fmaxf(red[0], red[1]), fmaxf(red[2], red[3]));
    m = fmaxf(m, fmaxf(fmaxf(red[4], red[5]), fmaxf(red[6], red[7])));
    float psum = 0.f;
    #pragma unroll
    for (int j = 0; j < 4; ++j) {
        float e = __expf(lv[j] - m);
        se[t + j * 256] = e;
        psum += e;
    }
    for (int o = 16; o; o >>= 1) psum += __shfl_xor_sync(0xffffffffu, psum, o);
    __syncthreads();
    if ((t & 31) == 0) red[t >> 5] = psum;
    __syncthreads();
    float inv = 1.f / ((red[0] + red[1]) + (red[2] + red[3])
                     + (red[4] + red[5]) + (red[6] + red[7]));

    const int colLane = t & 7;
    const int chunk = t >> 3;        // 0..31
    const int col = blockIdx.x * 8 + colLane;
    const float* Vc = V + (size_t)(chunk * 32) * N_DIM + col;
    float s = 0.f;
    #pragma unroll 8
    for (int c = 0; c < 32; ++c)
        s += se[chunk * 32 + c] * Vc[(size_t)c * N_DIM];
    part[chunk][colLane] = s;
    __syncthreads();
    if (t < 8) {
        float tot = 0.f;
        #pragma unroll
        for (int j = 0; j < 32; ++j) tot += part[j][t];
        g_memout[blockIdx.x * 8 + t] = tot * inv;
    }
}

// ---------------------------------------------------------------------------
// GEMM: out[m][n] = xh[m]·Wh[n] + 0.01*memout[n]
// fp16 inputs, fp32 accumulate, mma.sync m16n8k16, 2 CTAs/SM
// BOTH A and B fragments double-buffered (prefetch 1 ks ahead);
// grouped CTA rasterization; interleaved next-stage cp.async.
// ---------------------------------------------------------------------------
__device__ __forceinline__ void load_stage(char* smem, int s, int kt,
                                           int tid, int m0, int n0) {
    const int k0 = kt * BK;
    char* st = smem + s * STAGE_BYTES;
    const __half* gA = g_Xh + (size_t)m0 * K_DIM + k0;
    const __half* gB = g_Wh + (size_t)n0 * K_DIM + k0;
    #pragma unroll
    for (int i = 0; i < 4; ++i) {
        int idx = tid + i * 256;
        int row = idx >> 3, c = idx & 7;
        unsigned off = row * (PAD * 2) + c * 16;
        cp16(smem_u32(st + OFF_A + off), gA + (size_t)row * K_DIM + c * 8);
        cp16(smem_u32(st + OFF_B + off), gB + (size_t)row * K_DIM + c * 8);
    }
}

__global__ __launch_bounds__(256, 2)
void gemm_kernel(float* __restrict__ out) {
    extern __shared__ char smem[];
    const int tid  = threadIdx.x;
    const int lane = tid & 31;
    const int warp = tid >> 5;
    const int wm = warp & 1;          // 2 warps along M (64 rows each)
    const int wn = warp >> 1;         // 4 warps along N (32 cols each)

    // Grouped rasterization: 8 M-tiles x 32 N-tiles per group (256 CTAs)
    const int pid = blockIdx.y * gridDim.x + blockIdx.x;   // gridDim.x = 32
    const int first_m = (pid >> 8) << 3;                   // (pid/256)*8
    const int pid_m = first_m + (pid & 7);
    const int pid_n = (pid & 255) >> 3;
    const int m0 = pid_m * BM;
    const int n0 = pid_n * BN;

    float acc[4][4][4];
    #pragma unroll
    for (int mi = 0; mi < 4; ++mi)
        #pragma unroll
        for (int ni = 0; ni < 4; ++ni)
            #pragma unroll
            for (int r = 0; r < 4; ++r) acc[mi][ni][r] = 0.f;

    load_stage(smem, 0, 0, tid, m0, n0);
    asm volatile("cp.async.commit_group;");
    load_stage(smem, 1, 1, tid, m0, n0);
    asm volatile("cp.async.commit_group;");

    const int a_row = wm * 64 + (lane & 15);
    const int a_col = (lane >> 4) * 8;
    const int bg  = lane >> 3;
    const int b4_row = wn * 32 + ((bg >> 1) << 3) + (lane & 7);
    const int b4_col = (bg & 1) << 3;

    // per-thread cp.async chunk coordinates
    const int ld_row0 = tid >> 3;
    const int ld_c = tid & 7;

    for (int kt = 0; kt < KT; ++kt) {
        asm volatile("cp.async.wait_group %0;" :: "n"(STAGES - 2));
        __syncthreads();

        const bool do_pf = (kt + 2 < KT);
        char* stn = smem + ((kt + 2) % STAGES) * STAGE_BYTES;
        const int k0n = (kt + 2) * BK;
        const __half* gA = g_Xh + (size_t)m0 * K_DIM + k0n;
        const __half* gB = g_Wh + (size_t)n0 * K_DIM + k0n;

        char* st = smem + (kt % STAGES) * STAGE_BYTES;
        const __half* sA = reinterpret_cast<const __half*>(st + OFF_A);
        const __half* sB = reinterpret_cast<const __half*>(st + OFF_B);

        unsigned af[2][4][4];   // double-buffered A fragments
        unsigned bf[2][4][2];   // double-buffered B fragments

        auto load_A = [&](int ks, int buf) {
            #pragma unroll
            for (int mi = 0; mi < 4; ++mi) {
                unsigned ad = smem_u32(sA + (a_row + mi * 16) * PAD + ks * 16 + a_col);
                asm volatile("ldmatrix.sync.aligned.m8n8.x4.shared.b16 {%0,%1,%2,%3}, [%4];"
                             : "=r"(af[buf][mi][0]), "=r"(af[buf][mi][1]),
                               "=r"(af[buf][mi][2]), "=r"(af[buf][mi][3]) : "r"(ad));
            }
        };
        auto load_B = [&](int ks, int buf) {
            #pragma unroll
            for (int p = 0; p < 2; ++p) {
                unsigned bd = smem_u32(sB + (b4_row + p * 16) * PAD + ks * 16 + b4_col);
                asm volatile("ldmatrix.sync.aligned.m8n8.x4.shared.b16 {%0,%1,%2,%3}, [%4];"
                             : "=r"(bf[buf][2*p][0]),   "=r"(bf[buf][2*p][1]),
                               "=r"(bf[buf][2*p+1][0]), "=r"(bf[buf][2*p+1][1])
                             : "r"(bd));
            }
        };

        load_B(0, 0);
        load_A(0, 0);
        #pragma unroll
        for (int ks = 0; ks < 4; ++ks) {
            const int cur = ks & 1;
            if (ks < 3) {
                load_B(ks + 1, cur ^ 1);
                load_A(ks + 1, cur ^ 1);
            }
            // interleaved prefetch: 1/4 of the next stage per ks
            if (do_pf) {
                int row = ld_row0 + ks * 32;
                unsigned off = row * (PAD * 2) + ld_c * 16;
                cp16(smem_u32(stn + OFF_A + off), gA + (size_t)row * K_DIM + ld_c * 8);
                cp16(smem_u32(stn + OFF_B + off), gB + (size_t)row * K_DIM + ld_c * 8);
            }
            #pragma unroll
            for (int mi = 0; mi < 4; ++mi)
                #pragma unroll
                for (int ni = 0; ni < 4; ++ni)
                    asm volatile(
                        "mma.sync.aligned.m16n8k16.row.col.f32.f16.f16.f32 "
                        "{%0,%1,%2,%3}, {%4,%5,%6,%7}, {%8,%9}, {%0,%1,%2,%3};"
                        : "+f"(acc[mi][ni][0]), "+f"(acc[mi][ni][1]),
                          "+f"(acc[mi][ni][2]), "+f"(acc[mi][ni][3])
                        : "r"(af[cur][mi][0]), "r"(af[cur][mi][1]),
                          "r"(af[cur][mi][2]), "r"(af[cur][mi][3]),
                          "r"(bf[cur][ni][0]), "r"(bf[cur][ni][1]));
        }
        asm volatile("cp.async.commit_group;");
    }

    // Epilogue: add 0.01 * memory_out[n]
    const int g = lane >> 2, tg = lane & 3;
    #pragma unroll
    for (int ni = 0; ni < 4; ++ni) {
        int col = n0 + wn * 32 + ni * 8 + tg * 2;
        float b0 = 0.01f * g_memout[col];
        float b1 = 0.01f * g_memout[col + 1];
        #pragma unroll
        for (int mi = 0; mi < 4; ++mi) {
            int row = m0 + wm * 64 + mi * 16 + g;
            float2 v0 = make_float2(acc[mi][ni][0] + b0, acc[mi][ni][1] + b1);
            float2 v1 = make_float2(acc[mi][ni][2] + b0, acc[mi][ni][3] + b1);
            *reinterpret_cast<float2*>(out + (size_t)row * N_DIM + col) = v0;
            *reinterpret_cast<float2*>(out + (size_t)(row + 8) * N_DIM + col) = v1;
        }
    }
}

// ---------------------------------------------------------------------------
extern "C" void kernel_launch(void* const* d_in, const int* in_sizes, int n_in,
                              void* d_out, int out_size) {
    (void)in_sizes; (void)n_in; (void)out_size;
    const float* x  = (const float*)d_in[0];
    const float* w  = (const float*)d_in[1];
    const float* ws = (const float*)d_in[2];
    const float* mk = (const float*)d_in[3];
    const float* mv = (const float*)d_in[4];
    float* out = (float*)d_out;

    split_x_kernel<<<2048, 256>>>(x, (M_DIM * K_DIM) / 2);
    split_w_kernel<<<2048, 256>>>(w, ws, (N_DIM * K_DIM) / 2);

    logits_kernel<<<CAP_, 128>>>(mk, x);
    memout_kernel<<<N_DIM / 8, 256>>>(mv);

    cudaFuncSetAttribute(gemm_kernel, cudaFuncAttributeMaxDynamicSharedMemorySize,
                         SMEM_TOTAL);
    dim3 grid(N_DIM / BN, M_DIM / BM);   // 32 x 64 = 2048 CTAs
    gemm_kernel<<<grid, 256, SMEM_TOTAL>>>(out);
}

// round 14
// speedup vs baseline: 1.0271x; 1.0271x over previous
#include <cuda_runtime.h>
#include <cuda_fp16.h>
#include <cstdint>

// Problem dims
#define M_DIM 8192
#define N_DIM 4096
#define K_DIM 4096
#define CAP_  1024

// GEMM tiling (128x128, 256 thr, 2 CTAs/SM)
#define BM 128
#define BN 128
#define BK 64
#define KT (K_DIM / BK)            // 64
#define STAGES 3
#define PAD 72                     // smem row pitch in elements (144B rows)
#define TILE_BYTES (128 * PAD * 2) // 18432
#define STAGE_BYTES (2 * TILE_BYTES)          // A + B = 36864
#define SMEM_TOTAL (STAGES * STAGE_BYTES)     // 110592 -> 2 CTAs/SM

#define OFF_A 0
#define OFF_B TILE_BYTES

// ---------------------------------------------------------------------------
// Scratch (static device memory)
// ---------------------------------------------------------------------------
__device__ __half g_Xh[(size_t)M_DIM * K_DIM];   // x rounded to fp16
__device__ __half g_Wh[(size_t)N_DIM * K_DIM];   // w*scale rounded to fp16
__device__ float g_logits[CAP_];
__device__ float g_memout[N_DIM];

// ---------------------------------------------------------------------------
__device__ __forceinline__ unsigned smem_u32(const void* p) {
    return (unsigned)__cvta_generic_to_shared(p);
}
__device__ __forceinline__ void cp16(unsigned sa, const void* ga) {
    asm volatile("cp.async.cg.shared.global [%0], [%1], 16;" :: "r"(sa), "l"(ga));
}

// ---------------------------------------------------------------------------
// Prep: x -> fp16; w*scale -> fp16  (float4 vectorized)
// ---------------------------------------------------------------------------
__global__ void split_x_kernel(const float* __restrict__ x, int n4) {
    int i = blockIdx.x * blockDim.x + threadIdx.x;
    int stride = gridDim.x * blockDim.x;
    const float4* x4 = reinterpret_cast<const float4*>(x);
    uint2* h4 = reinterpret_cast<uint2*>(g_Xh);
    for (; i < n4; i += stride) {
        float4 v = x4[i];
        __half2 a = __floats2half2_rn(v.x, v.y);
        __half2 b = __floats2half2_rn(v.z, v.w);
        uint2 o;
        o.x = *reinterpret_cast<unsigned*>(&a);
        o.y = *reinterpret_cast<unsigned*>(&b);
        h4[i] = o;
    }
}

__global__ void split_w_kernel(const float* __restrict__ w,
                               const float* __restrict__ scale, int n4) {
    int i = blockIdx.x * blockDim.x + threadIdx.x;
    int stride = gridDim.x * blockDim.x;
    const float4* w4 = reinterpret_cast<const float4*>(w);
    uint2* h4 = reinterpret_cast<uint2*>(g_Wh);
    for (; i < n4; i += stride) {
        float4 v = w4[i];
        int row = i >> 10;             // (4*i)/4096
        float s = scale[row];
        __half2 a = __floats2half2_rn(v.x * s, v.y * s);
        __half2 b = __floats2half2_rn(v.z * s, v.w * s);
        uint2 o;
        o.x = *reinterpret_cast<unsigned*>(&a);
        o.y = *reinterpret_cast<unsigned*>(&b);
        h4[i] = o;
    }
}

// ---------------------------------------------------------------------------
// Associative memory
// ---------------------------------------------------------------------------
__global__ void logits_kernel(const float* __restrict__ keys,
                              const float* __restrict__ x) {
    int c = blockIdx.x;
    const float* kr = keys + (size_t)c * K_DIM;
    float s = 0.f;
    for (int i = threadIdx.x; i < K_DIM; i += 128) s += kr[i] * x[i];
    for (int o = 16; o; o >>= 1) s += __shfl_xor_sync(0xffffffffu, s, o);
    __shared__ float red[4];
    if ((threadIdx.x & 31) == 0) red[threadIdx.x >> 5] = s;
    __syncthreads();
    if (threadIdx.x == 0) g_logits[c] = red[0] + red[1] + red[2] + red[3];
}

// Fused softmax + attn@V: 512 CTAs x 256 threads; CTA owns 8 output cols;
// threads split CAP into 32 chunks of 32; deterministic smem reduce.
__global__ void memout_kernel(const float* __restrict__ V) {
    __shared__ float se[CAP_];
    __shared__ float red[8];
    __shared__ float part[32][9];
    const int t = threadIdx.x;       // 256 threads

    float lmax = -1e30f;
    float lv[4];
    #pragma unroll
    for (int j = 0; j < 4; ++j) {
        lv[j] = g_logits[t + j * 256];
        lmax = fmaxf(lmax, lv[j]);
    }
    for (int o = 16; o; o >>= 1) lmax = fmaxf(lmax, __shfl_xor_sync(0xffffffffu, lmax, o));
    if ((t & 31) == 0) red[t >> 5] = lmax;
    __syncthreads();
    float m = fmaxf(fmaxf(red[0], red[1]), fmaxf(red[2], red[3]));
    m = fmaxf(m, fmaxf(fmaxf(red[4], red[5]), fmaxf(red[6], red[7])));
    float psum = 0.f;
    #pragma unroll
    for (int j = 0; j < 4; ++j) {
        float e = __expf(lv[j] - m);
        se[t + j * 256] = e;
        psum += e;
    }
    for (int o = 16; o; o >>= 1) psum += __shfl_xor_sync(0xffffffffu, psum, o);
    __syncthreads();
    if ((t & 31) == 0) red[t >> 5] = psum;
    __syncthreads();
    float inv = 1.f / ((red[0] + red[1]) + (red[2] + red[3])
                     + (red[4] + red[5]) + (red[6] + red[7]));

    const int colLane = t & 7;
    const int chunk = t >> 3;        // 0..31
    const int col = blockIdx.x * 8 + colLane;
    const float* Vc = V + (size_t)(chunk * 32) * N_DIM + col;
    float s = 0.f;
    #pragma unroll 8
    for (int c = 0; c < 32; ++c)
        s += se[chunk * 32 + c] * Vc[(size_t)c * N_DIM];
    part[chunk][colLane] = s;
    __syncthreads();
    if (t < 8) {
        float tot = 0.f;
        #pragma unroll
        for (int j = 0; j < 32; ++j) tot += part[j][t];
        g_memout[blockIdx.x * 8 + t] = tot * inv;
    }
}

// ---------------------------------------------------------------------------
// GEMM: out[m][n] = xh[m]·Wh[n] + 0.01*memout[n]
// fp16 inputs, fp32 accumulate, mma.sync m16n8k16, 2 CTAs/SM
// A fragments prefetched one ks ahead; grouped CTA rasterization;
// next-stage cp.async issue interleaved across the 4 ks iterations.
// (R12 configuration — 696.6 us measured)
// ---------------------------------------------------------------------------
__device__ __forceinline__ void load_stage(char* smem, int s, int kt,
                                           int tid, int m0, int n0) {
    const int k0 = kt * BK;
    char* st = smem + s * STAGE_BYTES;
    const __half* gA = g_Xh + (size_t)m0 * K_DIM + k0;
    const __half* gB = g_Wh + (size_t)n0 * K_DIM + k0;
    #pragma unroll
    for (int i = 0; i < 4; ++i) {
        int idx = tid + i * 256;
        int row = idx >> 3, c = idx & 7;
        unsigned off = row * (PAD * 2) + c * 16;
        cp16(smem_u32(st + OFF_A + off), gA + (size_t)row * K_DIM + c * 8);
        cp16(smem_u32(st + OFF_B + off), gB + (size_t)row * K_DIM + c * 8);
    }
}

__global__ __launch_bounds__(256, 2)
void gemm_kernel(float* __restrict__ out) {
    extern __shared__ char smem[];
    const int tid  = threadIdx.x;
    const int lane = tid & 31;
    const int warp = tid >> 5;
    const int wm = warp & 1;          // 2 warps along M (64 rows each)
    const int wn = warp >> 1;         // 4 warps along N (32 cols each)

    // Grouped rasterization: 8 M-tiles x 32 N-tiles per group (256 CTAs)
    const int pid = blockIdx.y * gridDim.x + blockIdx.x;   // gridDim.x = 32
    const int first_m = (pid >> 8) << 3;                   // (pid/256)*8
    const int pid_m = first_m + (pid & 7);
    const int pid_n = (pid & 255) >> 3;
    const int m0 = pid_m * BM;
    const int n0 = pid_n * BN;

    float acc[4][4][4];
    #pragma unroll
    for (int mi = 0; mi < 4; ++mi)
        #pragma unroll
        for (int ni = 0; ni < 4; ++ni)
            #pragma unroll
            for (int r = 0; r < 4; ++r) acc[mi][ni][r] = 0.f;

    load_stage(smem, 0, 0, tid, m0, n0);
    asm volatile("cp.async.commit_group;");
    load_stage(smem, 1, 1, tid, m0, n0);
    asm volatile("cp.async.commit_group;");

    const int a_row = wm * 64 + (lane & 15);
    const int a_col = (lane >> 4) * 8;
    const int bg  = lane >> 3;
    const int b4_row = wn * 32 + ((bg >> 1) << 3) + (lane & 7);
    const int b4_col = (bg & 1) << 3;

    // per-thread cp.async chunk coordinates (row/c fixed across iters)
    const int ld_row0 = tid >> 3;          // rows tid/8 .. +32 per iter
    const int ld_c = tid & 7;

    for (int kt = 0; kt < KT; ++kt) {
        asm volatile("cp.async.wait_group %0;" :: "n"(STAGES - 2));
        __syncthreads();

        // next-stage pointers (issued piecewise inside the ks loop)
        const bool do_pf = (kt + 2 < KT);
        char* stn = smem + ((kt + 2) % STAGES) * STAGE_BYTES;
        const int k0n = (kt + 2) * BK;
        const __half* gA = g_Xh + (size_t)m0 * K_DIM + k0n;
        const __half* gB = g_Wh + (size_t)n0 * K_DIM + k0n;

        char* st = smem + (kt % STAGES) * STAGE_BYTES;
        const __half* sA = reinterpret_cast<const __half*>(st + OFF_A);
        const __half* sB = reinterpret_cast<const __half*>(st + OFF_B);

        unsigned af[2][4][4];   // double-buffered A fragments (prefetch 1 ks)

        auto load_A = [&](int ks, int buf) {
            #pragma unroll
            for (int mi = 0; mi < 4; ++mi) {
                unsigned ad = smem_u32(sA + (a_row + mi * 16) * PAD + ks * 16 + a_col);
                asm volatile("ldmatrix.sync.aligned.m8n8.x4.shared.b16 {%0,%1,%2,%3}, [%4];"
                             : "=r"(af[buf][mi][0]), "=r"(af[buf][mi][1]),
                               "=r"(af[buf][mi][2]), "=r"(af[buf][mi][3]) : "r"(ad));
            }
        };

        load_A(0, 0);
        #pragma unroll
        for (int ks = 0; ks < 4; ++ks) {
            const int cur = ks & 1;
            unsigned bf[4][2];
            #pragma unroll
            for (int p = 0; p < 2; ++p) {
                unsigned bd = smem_u32(sB + (b4_row + p * 16) * PAD + ks * 16 + b4_col);
                asm volatile("ldmatrix.sync.aligned.m8n8.x4.shared.b16 {%0,%1,%2,%3}, [%4];"
                             : "=r"(bf[2*p][0]),   "=r"(bf[2*p][1]),
                               "=r"(bf[2*p+1][0]), "=r"(bf[2*p+1][1])
                             : "r"(bd));
            }
            if (ks < 3) load_A(ks + 1, cur ^ 1);
            // interleaved prefetch: 1/4 of the next stage per ks
            if (do_pf) {
                int row = ld_row0 + ks * 32;
                unsigned off = row * (PAD * 2) + ld_c * 16;
                cp16(smem_u32(stn + OFF_A + off), gA + (size_t)row * K_DIM + ld_c * 8);
                cp16(smem_u32(stn + OFF_B + off), gB + (size_t)row * K_DIM + ld_c * 8);
            }
            #pragma unroll
            for (int mi = 0; mi < 4; ++mi)
                #pragma unroll
                for (int ni = 0; ni < 4; ++ni)
                    asm volatile(
                        "mma.sync.aligned.m16n8k16.row.col.f32.f16.f16.f32 "
                        "{%0,%1,%2,%3}, {%4,%5,%6,%7}, {%8,%9}, {%0,%1,%2,%3};"
                        : "+f"(acc[mi][ni][0]), "+f"(acc[mi][ni][1]),
                          "+f"(acc[mi][ni][2]), "+f"(acc[mi][ni][3])
                        : "r"(af[cur][mi][0]), "r"(af[cur][mi][1]),
                          "r"(af[cur][mi][2]), "r"(af[cur][mi][3]),
                          "r"(bf[ni][0]), "r"(bf[ni][1]));
        }
        asm volatile("cp.async.commit_group;");
    }

    // Epilogue: add 0.01 * memory_out[n]
    const int g = lane >> 2, tg = lane & 3;
    #pragma unroll
    for (int ni = 0; ni < 4; ++ni) {
        int col = n0 + wn * 32 + ni * 8 + tg * 2;
        float b0 = 0.01f * g_memout[col];
        float b1 = 0.01f * g_memout[col + 1];
        #pragma unroll
        for (int mi = 0; mi < 4; ++mi) {
            int row = m0 + wm * 64 + mi * 16 + g;
            float2 v0 = make_float2(acc[mi][ni][0] + b0, acc[mi][ni][1] + b1);
            float2 v1 = make_float2(acc[mi][ni][2] + b0, acc[mi][ni][3] + b1);
            *reinterpret_cast<float2*>(out + (size_t)row * N_DIM + col) = v0;
            *reinterpret_cast<float2*>(out + (size_t)(row + 8) * N_DIM + col) = v1;
        }
    }
}

// ---------------------------------------------------------------------------
extern "C" void kernel_launch(void* const* d_in, const int* in_sizes, int n_in,
                              void* d_out, int out_size) {
    (void)in_sizes; (void)n_in; (void)out_size;
    const float* x  = (const float*)d_in[0];
    const float* w  = (const float*)d_in[1];
    const float* ws = (const float*)d_in[2];
    const float* mk = (const float*)d_in[3];
    const float* mv = (const float*)d_in[4];
    float* out = (float*)d_out;

    split_x_kernel<<<2048, 256>>>(x, (M_DIM * K_DIM) / 4);
    split_w_kernel<<<2048, 256>>>(w, ws, (N_DIM * K_DIM) / 4);

    logits_kernel<<<CAP_, 128>>>(mk, x);
    memout_kernel<<<N_DIM / 8, 256>>>(mv);

    cudaFuncSetAttribute(gemm_kernel, cudaFuncAttributeMaxDynamicSharedMemorySize,
                         SMEM_TOTAL);
    dim3 grid(N_DIM / BN, M_DIM / BM);   // 32 x 64 = 2048 CTAs
    gemm_kernel<<<grid, 256, SMEM_TOTAL>>>(out);
}